// round 12
// baseline (speedup 1.0000x reference)
#include <cuda_runtime.h>
#include <cuda_fp16.h>
#include <cstdint>
#include <math.h>

#define Bt    2
#define S_LEN 8192
#define DIMD  1024
#define NH    16
#define NKV   4
#define HD    64
#define CHUNK 128
#define NC    64
#define NTOK  (Bt*S_LEN)
#define WROWS 2560          // Wq(1024) | Wk(256) | Wv(256) | Wo(1024)

// ---------------- scratch -----------------------------------------------------
__device__ float g_q[Bt*NH*S_LEN*HD];
__device__ float g_k[Bt*NKV*S_LEN*HD];
__device__ float g_v[Bt*NKV*S_LEN*HD];
__device__ float g_state[Bt*NH*NC*HD*HD];
__device__ float g_cos[S_LEN*32];
__device__ float g_sin[S_LEN*32];

__device__ __half g_xh[NTOK*DIMD];     // fp16 x
__device__ __half g_wh[WROWS*DIMD];    // fp16 weights
__device__ __half g_oh[NTOK*DIMD];     // fp16 attention output (token-major)

// ---------------- PTX helpers --------------------------------------------------
__device__ __forceinline__ uint32_t smem_u32(const void* p) {
    uint32_t a;
    asm("{ .reg .u64 t; cvta.to.shared.u64 t, %1; cvt.u32.u64 %0, t; }" : "=r"(a) : "l"(p));
    return a;
}
__device__ __forceinline__ void cp16(uint32_t dst, const void* src) {
    asm volatile("cp.async.cg.shared.global [%0], [%1], 16;" :: "r"(dst), "l"(src));
}
#define CP_COMMIT() asm volatile("cp.async.commit_group;" ::: "memory")
#define CP_WAIT(n)  asm volatile("cp.async.wait_group %0;" :: "n"(n) : "memory")

__device__ __forceinline__ void ldmx4(uint32_t r[4], uint32_t addr) {
    asm volatile("ldmatrix.sync.aligned.m8n8.x4.shared.b16 {%0,%1,%2,%3}, [%4];"
        : "=r"(r[0]), "=r"(r[1]), "=r"(r[2]), "=r"(r[3]) : "r"(addr));
}
__device__ __forceinline__ void mma_fp16(float c[4], const uint32_t a[4],
                                         uint32_t b0, uint32_t b1) {
    asm volatile("mma.sync.aligned.m16n8k16.row.col.f32.f16.f16.f32 "
        "{%0,%1,%2,%3}, {%4,%5,%6,%7}, {%8,%9}, {%0,%1,%2,%3};"
        : "+f"(c[0]), "+f"(c[1]), "+f"(c[2]), "+f"(c[3])
        : "r"(a[0]), "r"(a[1]), "r"(a[2]), "r"(a[3]), "r"(b0), "r"(b1));
}

// ---------------- fp32 -> fp16 converter ----------------------------------------
// dstSel: 0 -> g_xh, 1 -> g_wh
__global__ void cvt_half_kernel(const float* __restrict__ src,
                                int dstSel, int dstOff4, int n4) {
    int i = blockIdx.x * 256 + threadIdx.x;
    if (i >= n4) return;
    float4 v = ((const float4*)src)[i];
    __half* dst = (dstSel == 0) ? g_xh : g_wh;
    __half2* D = (__half2*)(dst) + 2 * (size_t)(dstOff4 + i);
    D[0] = __floats2half2_rn(v.x, v.y);
    D[1] = __floats2half2_rn(v.z, v.w);
}

// ---------------- mma.sync fp16 GEMM ---------------------------------------------
// C tile [128,128]; 8 warps, each 64x32 (2m x 4n). 2 CTAs/SM.
// MODE 0: A = g_xh, B = weight rows [colBase..), scatter -> q/k/v
// MODE 1: A = g_oh, B = weight rows [1536+colBase..), C -> Cout
#define APLANE 10240            // 128 rows * 80B pitch
#define STAGE_B (2*APLANE)      // 20480
#define NSTAGE 3

template <int MODE>
__global__ __launch_bounds__(256, 2) void mma_gemm(float* __restrict__ Cout) {
    extern __shared__ char smraw[];
    uint32_t sbase = smem_u32(smraw);
    int tid = threadIdx.x, lane = tid & 31, wid = tid >> 5;
    int wm = wid >> 2, wn = wid & 3;          // 2 m-warps x 4 n-warps
    int mBase = blockIdx.y * 128, colBase = blockIdx.x * 128;

    const __half* Ap = (MODE == 0 ? g_xh : g_oh) + (size_t)mBase * DIMD;
    int wrow = (MODE == 0 ? 0 : 1536) + colBase;
    const __half* Bp = g_wh + (size_t)wrow * DIMD;

    float acc[4][4][4];
    #pragma unroll
    for (int i = 0; i < 4; i++)
        #pragma unroll
        for (int j = 0; j < 4; j++)
            #pragma unroll
            for (int k = 0; k < 4; k++) acc[i][j][k] = 0.f;

    int ldrow = tid >> 2, ldseg = tid & 3;    // 64 rows x 4 16B-segs per pass
    uint32_t ldoff = (uint32_t)(ldrow * 80 + ldseg * 16);
    size_t goff = (size_t)ldrow * DIMD + ldseg * 8;

    // ---- async load of one K-chunk: A 128x32 fp16, B 128x32 fp16 ----
    auto issue = [&](int st, int kc) {
        uint32_t sb = sbase + st * STAGE_B;
        #pragma unroll
        for (int i = 0; i < 2; i++) {
            uint32_t off = ldoff + i * (64 * 80);
            size_t g = goff + (size_t)i * 64 * DIMD + kc * 32;
            cp16(sb + off,          Ap + g);
            cp16(sb + APLANE + off, Bp + g);
        }
    };

    issue(0, 0); CP_COMMIT();
    issue(1, 1); CP_COMMIT();
    int st = 0;
    for (int kc = 0; kc < 32; kc++) {
        if (kc + 2 < 32) issue((st + 2 >= NSTAGE) ? st + 2 - NSTAGE : st + 2, kc + 2);
        CP_COMMIT();
        CP_WAIT(2);
        __syncthreads();
        uint32_t sb = sbase + st * STAGE_B;

        #pragma unroll
        for (int kh = 0; kh < 2; kh++) {
            uint32_t b_h[2][4];
            #pragma unroll
            for (int nt = 0; nt < 2; nt++) {
                int nrow = wn * 32 + nt * 16 + ((lane >> 4) * 8) + (lane & 7);
                uint32_t bd = sb + APLANE +
                    (uint32_t)(nrow * 80 + kh * 32 + ((lane >> 3) & 1) * 16);
                ldmx4(b_h[nt], bd);
            }
            #pragma unroll
            for (int mt = 0; mt < 4; mt++) {
                int row = wm * 64 + mt * 16 + (lane & 15);
                uint32_t ad = sb + (uint32_t)(row * 80 + kh * 32 + (lane >> 4) * 16);
                uint32_t a_h[4];
                ldmx4(a_h, ad);
                #pragma unroll
                for (int nt = 0; nt < 2; nt++)
                    #pragma unroll
                    for (int nh = 0; nh < 2; nh++)
                        mma_fp16(acc[mt][nt * 2 + nh], a_h,
                                 b_h[nt][nh*2], b_h[nt][nh*2+1]);
            }
        }
        __syncthreads();
        st = (st + 1 >= NSTAGE) ? 0 : st + 1;
    }

    // ---- epilogue ----
    #pragma unroll
    for (int mt = 0; mt < 4; mt++) {
        int r0 = mBase + wm * 64 + mt * 16 + (lane >> 2);
        #pragma unroll
        for (int nf = 0; nf < 4; nf++) {
            int n = colBase + wn * 32 + nf * 8 + (lane & 3) * 2;
            float* c = acc[mt][nf];
            if (MODE == 1) {
                *(float2*)(Cout + (size_t)r0 * DIMD + n)       = make_float2(c[0], c[1]);
                *(float2*)(Cout + (size_t)(r0 + 8) * DIMD + n) = make_float2(c[2], c[3]);
            } else {
                #pragma unroll
                for (int rr = 0; rr < 2; rr++) {
                    int m = r0 + rr * 8;
                    int bb = m >> 13, ss = m & (S_LEN - 1);
                    float* dst;
                    if (n < 1024) {
                        int h = n >> 6, d = n & 63;
                        dst = g_q + ((size_t)(bb * NH + h) * S_LEN + ss) * HD + d;
                    } else if (n < 1280) {
                        int nn = n - 1024, h = nn >> 6, d = nn & 63;
                        dst = g_k + ((size_t)(bb * NKV + h) * S_LEN + ss) * HD + d;
                    } else {
                        int nn = n - 1280, h = nn >> 6, d = nn & 63;
                        dst = g_v + ((size_t)(bb * NKV + h) * S_LEN + ss) * HD + d;
                    }
                    *(float2*)dst = make_float2(c[rr * 2], c[rr * 2 + 1]);
                }
            }
        }
    }
}

// ---------------- RoPE tables ----------------------------------------------------
__global__ void rope_table_kernel() {
    int idx = blockIdx.x * 256 + threadIdx.x;
    if (idx >= S_LEN * 32) return;
    int s = idx >> 5, i = idx & 31;
    double inv = pow(10000.0, -(double)i / 32.0);
    double a = (double)s * inv;
    g_cos[idx] = (float)cos(a);
    g_sin[idx] = (float)sin(a);
}

__global__ void rope_apply_kernel() {
    int idx = blockIdx.x * 256 + threadIdx.x;
    const int NQp = Bt * NH  * S_LEN * 32;
    const int NKp = Bt * NKV * S_LEN * 32;
    float* ptr;
    if (idx < NQp) {
        ptr = g_q;
    } else if (idx < NQp + NKp) {
        idx -= NQp;
        ptr = g_k;
    } else return;
    int i  = idx & 31;
    int s  = (idx >> 5) & (S_LEN - 1);
    int bh = idx >> 18;
    float* base = ptr + (size_t)bh * (S_LEN * HD) + s * HD;
    float cc = g_cos[s * 32 + i];
    float ss = g_sin[s * 32 + i];
    float x1 = base[i];
    float x2 = base[i + 32];
    base[i]      = x1 * cc - x2 * ss;
    base[i + 32] = x2 * cc + x1 * ss;
}

// ---------------- Pass A: per-chunk KV contributions ------------------------------
__global__ __launch_bounds__(256) void kv_contrib_kernel() {
    extern __shared__ float sm[];
    float* ks = sm;
    float* vs = sm + CHUNK*HD;
    float* kd = vs + CHUNK*HD;
    int c = blockIdx.x, bh = blockIdx.y;
    int b = bh >> 4, h = bh & 15, kvh = h >> 2;
    float slope = exp2f(-0.5f * (float)(h + 1));
    const float* kp = g_k + ((size_t)(b*NKV + kvh)*S_LEN + c*CHUNK)*HD;
    const float* vp = g_v + ((size_t)(b*NKV + kvh)*S_LEN + c*CHUNK)*HD;
    int tid = threadIdx.x;
    for (int i = tid; i < CHUNK*HD/4; i += 256) {
        ((float4*)ks)[i] = ((const float4*)kp)[i];
        ((float4*)vs)[i] = ((const float4*)vp)[i];
    }
    if (tid < CHUNK) kd[tid] = expf(-slope * (float)(CHUNK - 1 - tid));
    __syncthreads();

    int d0 = (tid & 15) * 4, e0 = (tid >> 4) * 4;
    float acc[4][4];
    #pragma unroll
    for (int i = 0; i < 4; i++)
        #pragma unroll
        for (int j = 0; j < 4; j++) acc[i][j] = 0.f;

    for (int t = 0; t < CHUNK; t++) {
        float kdt = kd[t];
        float4 kk = *(const float4*)&ks[t*HD + d0];
        kk.x *= kdt; kk.y *= kdt; kk.z *= kdt; kk.w *= kdt;
        float4 vv = *(const float4*)&vs[t*HD + e0];
        acc[0][0] += kk.x*vv.x; acc[0][1] += kk.x*vv.y; acc[0][2] += kk.x*vv.z; acc[0][3] += kk.x*vv.w;
        acc[1][0] += kk.y*vv.x; acc[1][1] += kk.y*vv.y; acc[1][2] += kk.y*vv.z; acc[1][3] += kk.y*vv.w;
        acc[2][0] += kk.z*vv.x; acc[2][1] += kk.z*vv.y; acc[2][2] += kk.z*vv.z; acc[2][3] += kk.z*vv.w;
        acc[3][0] += kk.w*vv.x; acc[3][1] += kk.w*vv.y; acc[3][2] += kk.w*vv.z; acc[3][3] += kk.w*vv.w;
    }
    float* dst = g_state + (size_t)(bh*NC + c)*(HD*HD);
    #pragma unroll
    for (int i = 0; i < 4; i++)
        *(float4*)&dst[(d0 + i)*HD + e0] =
            make_float4(acc[i][0], acc[i][1], acc[i][2], acc[i][3]);
}

// ---------------- Pass B: exponential prefix scan ----------------------------------
__global__ void kv_scan_kernel() {
    int idx = blockIdx.x * 256 + threadIdx.x;
    if (idx >= 32 * HD * HD) return;
    int bh = idx >> 12;
    int el = idx & 4095;
    int h  = bh & 15;
    float bd = expf(-exp2f(-0.5f * (float)(h + 1)) * (float)CHUNK);
    float s = 0.f;
    float* p = g_state + (size_t)bh * NC * (HD*HD) + el;
    for (int c = 0; c < NC; c++) {
        float kvv = p[(size_t)c * (HD*HD)];
        p[(size_t)c * (HD*HD)] = s;
        s = bd * s + kvv;
    }
}

// ---------------- Pass C: per-chunk output (writes fp16 g_oh) ----------------------
__global__ __launch_bounds__(128) void attn_chunk_kernel() {
    extern __shared__ float sm[];
    float* ks = sm;
    float* vs = sm + 8192;
    float* Ss = sm + 16384;
    float* pw = sm + 20480;
    int c = blockIdx.x, bh = blockIdx.y;
    int b = bh >> 4, h = bh & 15, kvh = h >> 2;
    float slope = exp2f(-0.5f * (float)(h + 1));
    int tid = threadIdx.x;

    const float* kp = g_k + ((size_t)(b*NKV + kvh)*S_LEN + c*CHUNK)*HD;
    const float* vp = g_v + ((size_t)(b*NKV + kvh)*S_LEN + c*CHUNK)*HD;
    for (int i = tid; i < CHUNK*HD/4; i += 128) {
        ((float4*)ks)[i] = ((const float4*)kp)[i];
        ((float4*)vs)[i] = ((const float4*)vp)[i];
    }
    const float* Sp = g_state + (size_t)(bh*NC + c)*(HD*HD);
    for (int i = tid; i < HD*HD/4; i += 128)
        ((float4*)Ss)[i] = ((const float4*)Sp)[i];
    pw[tid] = expf(-slope * (float)tid);
    __syncthreads();

    int t = tid;
    float qr[64];
    const float* qp = g_q + ((size_t)(b*NH + h)*S_LEN + c*CHUNK + t)*HD;
    #pragma unroll
    for (int i = 0; i < 16; i++) {
        float4 v4 = ((const float4*)qp)[i];
        qr[4*i] = v4.x; qr[4*i+1] = v4.y; qr[4*i+2] = v4.z; qr[4*i+3] = v4.w;
    }
    float acc[64];
    #pragma unroll
    for (int i = 0; i < 64; i++) acc[i] = 0.f;

    for (int s = 0; s <= t; s++) {
        const float* krow = &ks[s*HD];
        float dot = 0.f;
        #pragma unroll
        for (int d = 0; d < 64; d += 4) {
            float4 k4 = *(const float4*)&krow[d];
            dot += qr[d]*k4.x + qr[d+1]*k4.y + qr[d+2]*k4.z + qr[d+3]*k4.w;
        }
        float w = dot * pw[t - s];
        const float* vrow = &vs[s*HD];
        #pragma unroll
        for (int e = 0; e < 64; e += 4) {
            float4 v4 = *(const float4*)&vrow[e];
            acc[e]   += w*v4.x; acc[e+1] += w*v4.y;
            acc[e+2] += w*v4.z; acc[e+3] += w*v4.w;
        }
    }

    float qd = expf(-slope * (float)(t + 1));
    #pragma unroll 4
    for (int d = 0; d < 64; d++) {
        float w = qr[d] * qd;
        const float* srow = &Ss[d*HD];
        #pragma unroll
        for (int e = 0; e < 64; e += 4) {
            float4 s4 = *(const float4*)&srow[e];
            acc[e]   += w*s4.x; acc[e+1] += w*s4.y;
            acc[e+2] += w*s4.z; acc[e+3] += w*s4.w;
        }
    }

    // write fp16 directly into GEMM2's A operand (token-major [tok][h*64+d])
    __half* op = g_oh + (((size_t)b*S_LEN + c*CHUNK + t)*NH + h)*HD;
    #pragma unroll
    for (int i = 0; i < 8; i++) {
        __half2 p0 = __floats2half2_rn(acc[8*i+0], acc[8*i+1]);
        __half2 p1 = __floats2half2_rn(acc[8*i+2], acc[8*i+3]);
        __half2 p2 = __floats2half2_rn(acc[8*i+4], acc[8*i+5]);
        __half2 p3 = __floats2half2_rn(acc[8*i+6], acc[8*i+7]);
        uint4 u;
        u.x = *(uint32_t*)&p0; u.y = *(uint32_t*)&p1;
        u.z = *(uint32_t*)&p2; u.w = *(uint32_t*)&p3;
        ((uint4*)op)[i] = u;
    }
}

// ---------------- launch --------------------------------------------------------------
extern "C" void kernel_launch(void* const* d_in, const int* in_sizes, int n_in,
                              void* d_out, int out_size) {
    const float* x  = (const float*)d_in[0];
    const float* Wq = (const float*)d_in[1];
    const float* Wk = (const float*)d_in[2];
    const float* Wv = (const float*)d_in[3];
    const float* Wo = (const float*)d_in[4];
    float* out = (float*)d_out;

    const int SMEM_G = NSTAGE * STAGE_B;                  // 61440
    const int SMEM_A = (CHUNK*HD*2 + CHUNK) * 4;          // 66048
    const int SMEM_C = (CHUNK*HD*2 + HD*HD + CHUNK) * 4;  // 82432
    cudaFuncSetAttribute(mma_gemm<0>, cudaFuncAttributeMaxDynamicSharedMemorySize, SMEM_G);
    cudaFuncSetAttribute(mma_gemm<1>, cudaFuncAttributeMaxDynamicSharedMemorySize, SMEM_G);
    cudaFuncSetAttribute(kv_contrib_kernel, cudaFuncAttributeMaxDynamicSharedMemorySize, SMEM_A);
    cudaFuncSetAttribute(attn_chunk_kernel, cudaFuncAttributeMaxDynamicSharedMemorySize, SMEM_C);

    {
        int n4 = NTOK * DIMD / 4;
        cvt_half_kernel<<<(n4 + 255)/256, 256>>>(x, 0, 0, n4);
        int w4 = 1024 * DIMD / 4;
        cvt_half_kernel<<<(w4 + 255)/256, 256>>>(Wq, 1, 0, w4);
        int k4 = 256 * DIMD / 4;
        cvt_half_kernel<<<(k4 + 255)/256, 256>>>(Wk, 1, 1024*DIMD/4, k4);
        cvt_half_kernel<<<(k4 + 255)/256, 256>>>(Wv, 1, 1280*DIMD/4, k4);
        cvt_half_kernel<<<(w4 + 255)/256, 256>>>(Wo, 1, 1536*DIMD/4, w4);
    }
    rope_table_kernel<<<(S_LEN*32 + 255)/256, 256>>>();

    // GEMM1: QKV projection (N = 1536)
    mma_gemm<0><<<dim3(12, NTOK/128), 256, SMEM_G>>>(nullptr);

    {
        int total = Bt*NH*S_LEN*32 + Bt*NKV*S_LEN*32;
        rope_apply_kernel<<<(total + 255)/256, 256>>>();
    }
    kv_contrib_kernel<<<dim3(NC, Bt*NH), 256, SMEM_A>>>();
    kv_scan_kernel<<<(Bt*NH*HD*HD + 255)/256, 256>>>();
    attn_chunk_kernel<<<dim3(NC, Bt*NH), 128, SMEM_C>>>();

    // GEMM2: output projection (N = 1024), A = g_oh written by attn_chunk
    mma_gemm<1><<<dim3(DIMD/128, NTOK/128), 256, SMEM_G>>>(out);
}

// round 13
// speedup vs baseline: 1.0007x; 1.0007x over previous
#include <cuda_runtime.h>
#include <cuda_fp16.h>
#include <cstdint>
#include <math.h>

#define Bt    2
#define S_LEN 8192
#define DIMD  1024
#define NH    16
#define NKV   4
#define HD    64
#define CHUNK 128
#define NC    64
#define NTOK  (Bt*S_LEN)
#define WROWS 2560          // Wq(1024) | Wk(256) | Wv(256) | Wo(1024)

// ---------------- scratch -----------------------------------------------------
__device__ float g_q[Bt*NH*S_LEN*HD];
__device__ float g_k[Bt*NKV*S_LEN*HD];
__device__ float g_v[Bt*NKV*S_LEN*HD];
__device__ float g_state[Bt*NH*NC*HD*HD];
__device__ float g_cos[S_LEN*32];
__device__ float g_sin[S_LEN*32];

__device__ __half g_xh[NTOK*DIMD];     // fp16 x
__device__ __half g_wh[WROWS*DIMD];    // fp16 weights
__device__ __half g_oh[NTOK*DIMD];     // fp16 attention output (token-major)

// ---------------- PTX helpers --------------------------------------------------
__device__ __forceinline__ uint32_t smem_u32(const void* p) {
    uint32_t a;
    asm("{ .reg .u64 t; cvta.to.shared.u64 t, %1; cvt.u32.u64 %0, t; }" : "=r"(a) : "l"(p));
    return a;
}
__device__ __forceinline__ void cp16(uint32_t dst, const void* src) {
    asm volatile("cp.async.cg.shared.global [%0], [%1], 16;" :: "r"(dst), "l"(src));
}
#define CP_COMMIT() asm volatile("cp.async.commit_group;" ::: "memory")
#define CP_WAIT(n)  asm volatile("cp.async.wait_group %0;" :: "n"(n) : "memory")

__device__ __forceinline__ void ldmx4(uint32_t r[4], uint32_t addr) {
    asm volatile("ldmatrix.sync.aligned.m8n8.x4.shared.b16 {%0,%1,%2,%3}, [%4];"
        : "=r"(r[0]), "=r"(r[1]), "=r"(r[2]), "=r"(r[3]) : "r"(addr));
}
__device__ __forceinline__ void mma_fp16(float c[4], const uint32_t a[4],
                                         uint32_t b0, uint32_t b1) {
    asm volatile("mma.sync.aligned.m16n8k16.row.col.f32.f16.f16.f32 "
        "{%0,%1,%2,%3}, {%4,%5,%6,%7}, {%8,%9}, {%0,%1,%2,%3};"
        : "+f"(c[0]), "+f"(c[1]), "+f"(c[2]), "+f"(c[3])
        : "r"(a[0]), "r"(a[1]), "r"(a[2]), "r"(a[3]), "r"(b0), "r"(b1));
}

// ---------------- fp32 -> fp16 converter ----------------------------------------
// dstSel: 0 -> g_xh, 1 -> g_wh
__global__ void cvt_half_kernel(const float* __restrict__ src,
                                int dstSel, int dstOff4, int n4) {
    int i = blockIdx.x * 256 + threadIdx.x;
    if (i >= n4) return;
    float4 v = ((const float4*)src)[i];
    __half* dst = (dstSel == 0) ? g_xh : g_wh;
    __half2* D = (__half2*)(dst) + 2 * (size_t)(dstOff4 + i);
    D[0] = __floats2half2_rn(v.x, v.y);
    D[1] = __floats2half2_rn(v.z, v.w);
}

// ---------------- mma.sync fp16 GEMM ---------------------------------------------
// C tile [128,128]; 8 warps, each 64x32 (2m x 4n). 2 CTAs/SM.
// MODE 0: A = g_xh, B = weight rows [colBase..), scatter -> q/k/v
// MODE 1: A = g_oh, B = weight rows [1536+colBase..), C -> Cout
#define APLANE 10240            // 128 rows * 80B pitch
#define STAGE_B (2*APLANE)      // 20480
#define NSTAGE 3

template <int MODE>
__global__ __launch_bounds__(256, 2) void mma_gemm(float* __restrict__ Cout) {
    extern __shared__ char smraw[];
    uint32_t sbase = smem_u32(smraw);
    int tid = threadIdx.x, lane = tid & 31, wid = tid >> 5;
    int wm = wid >> 2, wn = wid & 3;          // 2 m-warps x 4 n-warps
    int mBase = blockIdx.y * 128, colBase = blockIdx.x * 128;

    const __half* Ap = (MODE == 0 ? g_xh : g_oh) + (size_t)mBase * DIMD;
    int wrow = (MODE == 0 ? 0 : 1536) + colBase;
    const __half* Bp = g_wh + (size_t)wrow * DIMD;

    float acc[4][4][4];
    #pragma unroll
    for (int i = 0; i < 4; i++)
        #pragma unroll
        for (int j = 0; j < 4; j++)
            #pragma unroll
            for (int k = 0; k < 4; k++) acc[i][j][k] = 0.f;

    int ldrow = tid >> 2, ldseg = tid & 3;    // 64 rows x 4 16B-segs per pass
    uint32_t ldoff = (uint32_t)(ldrow * 80 + ldseg * 16);
    size_t goff = (size_t)ldrow * DIMD + ldseg * 8;

    // ---- async load of one K-chunk: A 128x32 fp16, B 128x32 fp16 ----
    auto issue = [&](int st, int kc) {
        uint32_t sb = sbase + st * STAGE_B;
        #pragma unroll
        for (int i = 0; i < 2; i++) {
            uint32_t off = ldoff + i * (64 * 80);
            size_t g = goff + (size_t)i * 64 * DIMD + kc * 32;
            cp16(sb + off,          Ap + g);
            cp16(sb + APLANE + off, Bp + g);
        }
    };

    issue(0, 0); CP_COMMIT();
    issue(1, 1); CP_COMMIT();
    int st = 0;
    for (int kc = 0; kc < 32; kc++) {
        if (kc + 2 < 32) issue((st + 2 >= NSTAGE) ? st + 2 - NSTAGE : st + 2, kc + 2);
        CP_COMMIT();
        CP_WAIT(2);
        __syncthreads();
        uint32_t sb = sbase + st * STAGE_B;

        #pragma unroll
        for (int kh = 0; kh < 2; kh++) {
            uint32_t b_h[2][4];
            #pragma unroll
            for (int nt = 0; nt < 2; nt++) {
                int nrow = wn * 32 + nt * 16 + ((lane >> 4) * 8) + (lane & 7);
                uint32_t bd = sb + APLANE +
                    (uint32_t)(nrow * 80 + kh * 32 + ((lane >> 3) & 1) * 16);
                ldmx4(b_h[nt], bd);
            }
            #pragma unroll
            for (int mt = 0; mt < 4; mt++) {
                int row = wm * 64 + mt * 16 + (lane & 15);
                uint32_t ad = sb + (uint32_t)(row * 80 + kh * 32 + (lane >> 4) * 16);
                uint32_t a_h[4];
                ldmx4(a_h, ad);
                #pragma unroll
                for (int nt = 0; nt < 2; nt++)
                    #pragma unroll
                    for (int nh = 0; nh < 2; nh++)
                        mma_fp16(acc[mt][nt * 2 + nh], a_h,
                                 b_h[nt][nh*2], b_h[nt][nh*2+1]);
            }
        }
        __syncthreads();
        st = (st + 1 >= NSTAGE) ? 0 : st + 1;
    }

    // ---- epilogue ----
    #pragma unroll
    for (int mt = 0; mt < 4; mt++) {
        int r0 = mBase + wm * 64 + mt * 16 + (lane >> 2);
        #pragma unroll
        for (int nf = 0; nf < 4; nf++) {
            int n = colBase + wn * 32 + nf * 8 + (lane & 3) * 2;
            float* c = acc[mt][nf];
            if (MODE == 1) {
                *(float2*)(Cout + (size_t)r0 * DIMD + n)       = make_float2(c[0], c[1]);
                *(float2*)(Cout + (size_t)(r0 + 8) * DIMD + n) = make_float2(c[2], c[3]);
            } else {
                #pragma unroll
                for (int rr = 0; rr < 2; rr++) {
                    int m = r0 + rr * 8;
                    int bb = m >> 13, ss = m & (S_LEN - 1);
                    float* dst;
                    if (n < 1024) {
                        int h = n >> 6, d = n & 63;
                        dst = g_q + ((size_t)(bb * NH + h) * S_LEN + ss) * HD + d;
                    } else if (n < 1280) {
                        int nn = n - 1024, h = nn >> 6, d = nn & 63;
                        dst = g_k + ((size_t)(bb * NKV + h) * S_LEN + ss) * HD + d;
                    } else {
                        int nn = n - 1280, h = nn >> 6, d = nn & 63;
                        dst = g_v + ((size_t)(bb * NKV + h) * S_LEN + ss) * HD + d;
                    }
                    *(float2*)dst = make_float2(c[rr * 2], c[rr * 2 + 1]);
                }
            }
        }
    }
}

// ---------------- RoPE tables ----------------------------------------------------
__global__ void rope_table_kernel() {
    int idx = blockIdx.x * 256 + threadIdx.x;
    if (idx >= S_LEN * 32) return;
    int s = idx >> 5, i = idx & 31;
    double inv = pow(10000.0, -(double)i / 32.0);
    double a = (double)s * inv;
    g_cos[idx] = (float)cos(a);
    g_sin[idx] = (float)sin(a);
}

__global__ void rope_apply_kernel() {
    int idx = blockIdx.x * 256 + threadIdx.x;
    const int NQp = Bt * NH  * S_LEN * 32;
    const int NKp = Bt * NKV * S_LEN * 32;
    float* ptr;
    if (idx < NQp) {
        ptr = g_q;
    } else if (idx < NQp + NKp) {
        idx -= NQp;
        ptr = g_k;
    } else return;
    int i  = idx & 31;
    int s  = (idx >> 5) & (S_LEN - 1);
    int bh = idx >> 18;
    float* base = ptr + (size_t)bh * (S_LEN * HD) + s * HD;
    float cc = g_cos[s * 32 + i];
    float ss = g_sin[s * 32 + i];
    float x1 = base[i];
    float x2 = base[i + 32];
    base[i]      = x1 * cc - x2 * ss;
    base[i + 32] = x2 * cc + x1 * ss;
}

// ---------------- Pass A: per-chunk KV contributions ------------------------------
__global__ __launch_bounds__(256) void kv_contrib_kernel() {
    extern __shared__ float sm[];
    float* ks = sm;
    float* vs = sm + CHUNK*HD;
    float* kd = vs + CHUNK*HD;
    int c = blockIdx.x, bh = blockIdx.y;
    int b = bh >> 4, h = bh & 15, kvh = h >> 2;
    float slope = exp2f(-0.5f * (float)(h + 1));
    const float* kp = g_k + ((size_t)(b*NKV + kvh)*S_LEN + c*CHUNK)*HD;
    const float* vp = g_v + ((size_t)(b*NKV + kvh)*S_LEN + c*CHUNK)*HD;
    int tid = threadIdx.x;
    for (int i = tid; i < CHUNK*HD/4; i += 256) {
        ((float4*)ks)[i] = ((const float4*)kp)[i];
        ((float4*)vs)[i] = ((const float4*)vp)[i];
    }
    if (tid < CHUNK) kd[tid] = expf(-slope * (float)(CHUNK - 1 - tid));
    __syncthreads();

    int d0 = (tid & 15) * 4, e0 = (tid >> 4) * 4;
    float acc[4][4];
    #pragma unroll
    for (int i = 0; i < 4; i++)
        #pragma unroll
        for (int j = 0; j < 4; j++) acc[i][j] = 0.f;

    for (int t = 0; t < CHUNK; t++) {
        float kdt = kd[t];
        float4 kk = *(const float4*)&ks[t*HD + d0];
        kk.x *= kdt; kk.y *= kdt; kk.z *= kdt; kk.w *= kdt;
        float4 vv = *(const float4*)&vs[t*HD + e0];
        acc[0][0] += kk.x*vv.x; acc[0][1] += kk.x*vv.y; acc[0][2] += kk.x*vv.z; acc[0][3] += kk.x*vv.w;
        acc[1][0] += kk.y*vv.x; acc[1][1] += kk.y*vv.y; acc[1][2] += kk.y*vv.z; acc[1][3] += kk.y*vv.w;
        acc[2][0] += kk.z*vv.x; acc[2][1] += kk.z*vv.y; acc[2][2] += kk.z*vv.z; acc[2][3] += kk.z*vv.w;
        acc[3][0] += kk.w*vv.x; acc[3][1] += kk.w*vv.y; acc[3][2] += kk.w*vv.z; acc[3][3] += kk.w*vv.w;
    }
    float* dst = g_state + (size_t)(bh*NC + c)*(HD*HD);
    #pragma unroll
    for (int i = 0; i < 4; i++)
        *(float4*)&dst[(d0 + i)*HD + e0] =
            make_float4(acc[i][0], acc[i][1], acc[i][2], acc[i][3]);
}

// ---------------- Pass B: exponential prefix scan ----------------------------------
__global__ void kv_scan_kernel() {
    int idx = blockIdx.x * 256 + threadIdx.x;
    if (idx >= 32 * HD * HD) return;
    int bh = idx >> 12;
    int el = idx & 4095;
    int h  = bh & 15;
    float bd = expf(-exp2f(-0.5f * (float)(h + 1)) * (float)CHUNK);
    float s = 0.f;
    float* p = g_state + (size_t)bh * NC * (HD*HD) + el;
    for (int c = 0; c < NC; c++) {
        float kvv = p[(size_t)c * (HD*HD)];
        p[(size_t)c * (HD*HD)] = s;
        s = bd * s + kvv;
    }
}

// ---------------- Pass C: per-chunk output (writes fp16 g_oh) ----------------------
__global__ __launch_bounds__(128) void attn_chunk_kernel() {
    extern __shared__ float sm[];
    float* ks = sm;
    float* vs = sm + 8192;
    float* Ss = sm + 16384;
    float* pw = sm + 20480;
    int c = blockIdx.x, bh = blockIdx.y;
    int b = bh >> 4, h = bh & 15, kvh = h >> 2;
    float slope = exp2f(-0.5f * (float)(h + 1));
    int tid = threadIdx.x;

    const float* kp = g_k + ((size_t)(b*NKV + kvh)*S_LEN + c*CHUNK)*HD;
    const float* vp = g_v + ((size_t)(b*NKV + kvh)*S_LEN + c*CHUNK)*HD;
    for (int i = tid; i < CHUNK*HD/4; i += 128) {
        ((float4*)ks)[i] = ((const float4*)kp)[i];
        ((float4*)vs)[i] = ((const float4*)vp)[i];
    }
    const float* Sp = g_state + (size_t)(bh*NC + c)*(HD*HD);
    for (int i = tid; i < HD*HD/4; i += 128)
        ((float4*)Ss)[i] = ((const float4*)Sp)[i];
    pw[tid] = expf(-slope * (float)tid);
    __syncthreads();

    int t = tid;
    float qr[64];
    const float* qp = g_q + ((size_t)(b*NH + h)*S_LEN + c*CHUNK + t)*HD;
    #pragma unroll
    for (int i = 0; i < 16; i++) {
        float4 v4 = ((const float4*)qp)[i];
        qr[4*i] = v4.x; qr[4*i+1] = v4.y; qr[4*i+2] = v4.z; qr[4*i+3] = v4.w;
    }
    float acc[64];
    #pragma unroll
    for (int i = 0; i < 64; i++) acc[i] = 0.f;

    for (int s = 0; s <= t; s++) {
        const float* krow = &ks[s*HD];
        float dot = 0.f;
        #pragma unroll
        for (int d = 0; d < 64; d += 4) {
            float4 k4 = *(const float4*)&krow[d];
            dot += qr[d]*k4.x + qr[d+1]*k4.y + qr[d+2]*k4.z + qr[d+3]*k4.w;
        }
        float w = dot * pw[t - s];
        const float* vrow = &vs[s*HD];
        #pragma unroll
        for (int e = 0; e < 64; e += 4) {
            float4 v4 = *(const float4*)&vrow[e];
            acc[e]   += w*v4.x; acc[e+1] += w*v4.y;
            acc[e+2] += w*v4.z; acc[e+3] += w*v4.w;
        }
    }

    float qd = expf(-slope * (float)(t + 1));
    #pragma unroll 4
    for (int d = 0; d < 64; d++) {
        float w = qr[d] * qd;
        const float* srow = &Ss[d*HD];
        #pragma unroll
        for (int e = 0; e < 64; e += 4) {
            float4 s4 = *(const float4*)&srow[e];
            acc[e]   += w*s4.x; acc[e+1] += w*s4.y;
            acc[e+2] += w*s4.z; acc[e+3] += w*s4.w;
        }
    }

    // write fp16 directly into GEMM2's A operand (token-major [tok][h*64+d])
    __half* op = g_oh + (((size_t)b*S_LEN + c*CHUNK + t)*NH + h)*HD;
    #pragma unroll
    for (int i = 0; i < 8; i++) {
        __half2 p0 = __floats2half2_rn(acc[8*i+0], acc[8*i+1]);
        __half2 p1 = __floats2half2_rn(acc[8*i+2], acc[8*i+3]);
        __half2 p2 = __floats2half2_rn(acc[8*i+4], acc[8*i+5]);
        __half2 p3 = __floats2half2_rn(acc[8*i+6], acc[8*i+7]);
        uint4 u;
        u.x = *(uint32_t*)&p0; u.y = *(uint32_t*)&p1;
        u.z = *(uint32_t*)&p2; u.w = *(uint32_t*)&p3;
        ((uint4*)op)[i] = u;
    }
}

// ---------------- launch --------------------------------------------------------------
extern "C" void kernel_launch(void* const* d_in, const int* in_sizes, int n_in,
                              void* d_out, int out_size) {
    const float* x  = (const float*)d_in[0];
    const float* Wq = (const float*)d_in[1];
    const float* Wk = (const float*)d_in[2];
    const float* Wv = (const float*)d_in[3];
    const float* Wo = (const float*)d_in[4];
    float* out = (float*)d_out;

    const int SMEM_G = NSTAGE * STAGE_B;                  // 61440
    const int SMEM_A = (CHUNK*HD*2 + CHUNK) * 4;          // 66048
    const int SMEM_C = (CHUNK*HD*2 + HD*HD + CHUNK) * 4;  // 82432
    cudaFuncSetAttribute(mma_gemm<0>, cudaFuncAttributeMaxDynamicSharedMemorySize, SMEM_G);
    cudaFuncSetAttribute(mma_gemm<1>, cudaFuncAttributeMaxDynamicSharedMemorySize, SMEM_G);
    cudaFuncSetAttribute(kv_contrib_kernel, cudaFuncAttributeMaxDynamicSharedMemorySize, SMEM_A);
    cudaFuncSetAttribute(attn_chunk_kernel, cudaFuncAttributeMaxDynamicSharedMemorySize, SMEM_C);

    {
        int n4 = NTOK * DIMD / 4;
        cvt_half_kernel<<<(n4 + 255)/256, 256>>>(x, 0, 0, n4);
        int w4 = 1024 * DIMD / 4;
        cvt_half_kernel<<<(w4 + 255)/256, 256>>>(Wq, 1, 0, w4);
        int k4 = 256 * DIMD / 4;
        cvt_half_kernel<<<(k4 + 255)/256, 256>>>(Wk, 1, 1024*DIMD/4, k4);
        cvt_half_kernel<<<(k4 + 255)/256, 256>>>(Wv, 1, 1280*DIMD/4, k4);
        cvt_half_kernel<<<(w4 + 255)/256, 256>>>(Wo, 1, 1536*DIMD/4, w4);
    }
    rope_table_kernel<<<(S_LEN*32 + 255)/256, 256>>>();

    // GEMM1: QKV projection (N = 1536)
    mma_gemm<0><<<dim3(12, NTOK/128), 256, SMEM_G>>>(nullptr);

    {
        int total = Bt*NH*S_LEN*32 + Bt*NKV*S_LEN*32;
        rope_apply_kernel<<<(total + 255)/256, 256>>>();
    }
    kv_contrib_kernel<<<dim3(NC, Bt*NH), 256, SMEM_A>>>();
    kv_scan_kernel<<<(Bt*NH*HD*HD + 255)/256, 256>>>();
    attn_chunk_kernel<<<dim3(NC, Bt*NH), 128, SMEM_C>>>();

    // GEMM2: output projection (N = 1024), A = g_oh written by attn_chunk
    mma_gemm<1><<<dim3(DIMD/128, NTOK/128), 256, SMEM_G>>>(out);
}